// round 5
// baseline (speedup 1.0000x reference)
#include <cuda_runtime.h>
#include <math.h>

// Problem constants (fixed by the dataset)
#define MM 512
#define NN 256
#define DD 64
#define EPSV 1e-6f
#define INFV 1e30f
#define SENTU 0xFFC00001u   // NaN payload; never produced by the DP arithmetic

// ---------------- device scratch (no allocations allowed) ----------------
__device__ float g_dists[MM * NN];          // d[m][n]
__device__ float g_qT[NN * (NN + 1)];       // qT[nb][i] = q[i][nb]
__device__ float g_p[NN + 1];               // reachability
__device__ float g_w[NN * NN];              // w[n][nb] (0 where not an edge)
__device__ float g_fw[NN];                  // final weights p_back[N][:]
__device__ float g_C[MM * NN];              // DP table (sentinel-initialized)

// ---------------- tiny asm helpers ----------------
__device__ __forceinline__ unsigned ldcg_u32(const float* p) {
    unsigned v;
    asm volatile("ld.global.cg.b32 %0, [%1];" : "=r"(v) : "l"(p));
    return v;
}
__device__ __forceinline__ void stcg_f32(float* p, float v) {
    asm volatile("st.global.cg.b32 [%0], %1;" :: "l"(p), "f"(v));
}
__device__ __forceinline__ unsigned long long lds_vol64(unsigned addr) {
    unsigned long long v;
    asm volatile("ld.volatile.shared.b64 %0, [%1];" : "=l"(v) : "r"(addr));
    return v;
}
__device__ __forceinline__ void sts_vol64(unsigned addr, unsigned long long v) {
    asm volatile("st.volatile.shared.b64 [%0], %1;" :: "r"(addr), "l"(v));
}

// ---------------- stage 0: sentinel-fill C (every launch; graph-replay safe) ----
__global__ void init_kernel() {
    int t = blockIdx.x * 256 + threadIdx.x;
    if (t < MM * NN) g_C[t] = __uint_as_float(SENTU);
}

// ---------------- stage 1: pairwise L2 distances ----------
__global__ void __launch_bounds__(256) dist_kernel(const float* __restrict__ x,
                                                   const float* __restrict__ y) {
    __shared__ float xs[32][DD + 1];
    __shared__ float ys[64][DD + 1];
    int m0 = blockIdx.x * 32;
    int n0 = blockIdx.y * 64;
    int t = threadIdx.x;

    for (int i = t; i < 32 * DD; i += 256) xs[i / DD][i % DD] = x[(m0 + i / DD) * DD + i % DD];
    for (int i = t; i < 64 * DD; i += 256) ys[i / DD][i % DD] = y[(n0 + i / DD) * DD + i % DD];
    __syncthreads();

    int tn = t & 63;
    int tm = t >> 6;
    float acc[8];
#pragma unroll
    for (int r = 0; r < 8; r++) acc[r] = 0.f;

    for (int k = 0; k < DD; k++) {
        float yv = ys[tn][k];
#pragma unroll
        for (int r = 0; r < 8; r++) {
            float d = xs[tm * 8 + r][k] - yv;
            acc[r] = fmaf(d, d, acc[r]);
        }
    }
#pragma unroll
    for (int r = 0; r < 8; r++)
        g_dists[(m0 + tm * 8 + r) * NN + (n0 + tn)] = sqrtf(acc[r]);
}

// ---------------- stage 2a: transpose q for coalesced scan ----------------
__global__ void transpose_q(const float* __restrict__ q) {
    int idx = blockIdx.x * 256 + threadIdx.x;
    if (idx < NN * (NN + 1)) {
        int nb = idx / (NN + 1);
        int i  = idx % (NN + 1);
        g_qT[idx] = q[i * NN + nb];
    }
}

// ---------------- stage 2b: reachability scan, ONE barrier per step --------
// p values live in registers; at step nb only thread nb+1 publishes its value
// (the single value step nb+1 will read). ps[nb] is read-broadcast.
__global__ void __launch_bounds__(320) scan_kernel() {
    __shared__ float ps[NN + 1];
    int t = threadIdx.x;
    bool act = (t <= NN);
    float pt = (t == 0) ? 1.f : 0.f;
    if (t == 0) ps[0] = 1.f;
    __syncthreads();

    float q0 = act ? g_qT[0 * (NN + 1) + t] : 0.f;
    float q1 = act ? g_qT[1 * (NN + 1) + t] : 0.f;
    float q2 = act ? g_qT[2 * (NN + 1) + t] : 0.f;
    float q3 = act ? g_qT[3 * (NN + 1) + t] : 0.f;

#define SCAN_STEP(NB, QV)                                   \
    {                                                       \
        float pv = ps[(NB)];                                \
        pt = fmaf(pv, (QV), pt);                            \
        if (t == (NB) + 1) ps[t] = pt;                      \
        __syncthreads();                                    \
    }

    for (int nb = 0; nb < NN; nb += 4) {
        float t0 = (act && nb + 4 < NN) ? g_qT[(nb + 4) * (NN + 1) + t] : 0.f;
        float t1 = (act && nb + 5 < NN) ? g_qT[(nb + 5) * (NN + 1) + t] : 0.f;
        float t2 = (act && nb + 6 < NN) ? g_qT[(nb + 6) * (NN + 1) + t] : 0.f;
        float t3 = (act && nb + 7 < NN) ? g_qT[(nb + 7) * (NN + 1) + t] : 0.f;

        SCAN_STEP(nb + 0, q0);
        SCAN_STEP(nb + 1, q1);
        SCAN_STEP(nb + 2, q2);
        SCAN_STEP(nb + 3, q3);

        q0 = t0; q1 = t1; q2 = t2; q3 = t3;
    }
#undef SCAN_STEP
    if (act) g_p[t] = pt;
}

// ---------------- stage 3: mixing weights + terminal weights ---------------
__global__ void weights_kernel(const float* __restrict__ q) {
    int idx = blockIdx.x * 256 + threadIdx.x;  // N*N threads
    int n  = idx >> 8;
    int nb = idx & 255;
    float pb = g_p[nb] * q[n * NN + nb] / (g_p[n] + EPSV);
    g_w[idx] = (nb < n && pb > 0.f) ? pb : 0.f;
    if (n == 0) {
        g_fw[nb] = g_p[nb] * q[NN * NN + nb] / (g_p[NN] + EPSV);
    }
}

// ---------------- stage 4: wavefront DP, smem ring + L2 sentinels ----------
// 8 CTAs x 32 warps; warp w of CTA b owns column n = 32b + w.
// Intra-CTA handoff: 8-byte volatile smem slot (row-tag, value); every poll
// loop backs off with __nanosleep (the R2 starvation fix). Inter-CTA + prefix
// chunks: sentinel-valued g_C in L2 via st.cg/ld.cg with verify-retry that
// ONLY waits on cells of strictly earlier columns (the R3 deadlock fix).
// Next-row global loads are issued before computing the current row so their
// ~470cy latency hides under compute + the next smem poll.
__global__ void __launch_bounds__(1024, 1) dp_kernel() {
    extern __shared__ unsigned long long ring[];   // [MM][32] packed (m, value)
    const int lane = threadIdx.x & 31;
    const int wid  = threadIdx.x >> 5;
    const int b    = blockIdx.x;
    const int n    = b * 32 + wid;

    for (int i = threadIdx.x; i < MM * 32; i += 1024)
        ring[i] = 0xFFFFFFFF00000000ull;
    __syncthreads();

    const unsigned ring_base = (unsigned)__cvta_generic_to_shared(ring);

    if (b == 0 && wid == 0) {
        // column 0: running sum of d[m][0] via warp inclusive scan.
        // Publishes 32 rows per pass: global st.cg + own ring slot [m][0].
        float run = 0.f;
        for (int mb = 0; mb < MM; mb += 32) {
            float dv = g_dists[(mb + lane) * NN];
#pragma unroll
            for (int off = 1; off < 32; off <<= 1) {
                float t = __shfl_up_sync(0xffffffffu, dv, off);
                if (lane >= off) dv += t;
            }
            float val = run + dv;
            int m = mb + lane;
            stcg_f32(&g_C[m * NN], val);
            unsigned long long pk =
                ((unsigned long long)(unsigned)m << 32) |
                (unsigned long long)__float_as_uint(val);
            sts_vol64(ring_base + (unsigned)(m * 32) * 8u, pk);
            run = __shfl_sync(0xffffffffu, val, 31);
        }
        return;
    }

    float wreg[8], Breg[8], Pprev[8];
#pragma unroll
    for (int j = 0; j < 8; j++) {
        int idx = j * 32 + lane;
        wreg[j]  = (idx < n) ? g_w[n * NN + idx] : 0.f;
        Breg[j]  = INFV;
        Pprev[j] = INFV;
    }

    // prologue: issue speculative loads for row 0 chunks owned by earlier CTAs
    unsigned cu[8];
#pragma unroll
    for (int j = 0; j < 8; j++)
        if (j < b) cu[j] = ldcg_u32(&g_C[j * 32 + lane]);
    float dmn = __ldg(&g_dists[n]);

    for (int m = 0; m < MM; m++) {
        unsigned cub = 0;   // chunk b values (own-CTA columns, lanes < wid)

        if (wid > 0) {
            // poll ring slots of all lower warps in this CTA for row m
            unsigned maddr = ring_base + (unsigned)(m * 32 + lane) * 8u;
            for (;;) {
                unsigned long long pk = (lane < wid)
                    ? lds_vol64(maddr)
                    : ((unsigned long long)(unsigned)m << 32);
                if (__all_sync(0xffffffffu, (unsigned)(pk >> 32) == (unsigned)m)) {
                    cub = (unsigned)pk;
                    break;
                }
                __nanosleep(20);
            }
        } else {
            // wid==0, b>0: poll boundary column 32b-1 in L2 (scalar broadcast)
            const float* paddr = &g_C[m * NN + 32 * b - 1];
            unsigned pv = ldcg_u32(paddr);
            while (pv == SENTU) {
                __nanosleep(40);
                pv = ldcg_u32(paddr);
            }
        }

        // verify-retry global chunks: all their cells belong to columns < 32b <= n
        for (;;) {
            int again = 0;
#pragma unroll
            for (int j = 0; j < 8; j++) {
                if (j < b) {
                    bool need = (cu[j] == SENTU);
                    if (__any_sync(0xffffffffu, need)) {
                        if (need) cu[j] = ldcg_u32(&g_C[m * NN + j * 32 + lane]);
                        again = 1;
                    }
                }
            }
            if (!again) break;
            __nanosleep(20);
        }

        // snapshot values, then immediately issue next-row loads (prefetch)
        float ccv[8];
#pragma unroll
        for (int j = 0; j < 8; j++)
            if (j < b) ccv[j] = __uint_as_float(cu[j]);
        float dnext = 0.f;
        if (m + 1 < MM) {
#pragma unroll
            for (int j = 0; j < 8; j++)
                if (j < b) cu[j] = ldcg_u32(&g_C[(m + 1) * NN + j * 32 + lane]);
            dnext = __ldg(&g_dists[(m + 1) * NN + n]);
        }

        // compute cell (m, n)
        float acc = 0.f;
#pragma unroll
        for (int j = 0; j < 8; j++) {
            if (j < b) {
                float cc = ccv[j];
                float mn = fminf(cc, fminf(Pprev[j], Breg[j]));
                float cb = dmn + mn;
                if (wreg[j] > 0.f) { acc += wreg[j] * cb; Breg[j] = cb; }
                Pprev[j] = cc;
            } else if (j == b) {
                if (lane < wid) {
                    float cc = __uint_as_float(cub);
                    float mn = fminf(cc, fminf(Pprev[j], Breg[j]));
                    float cb = dmn + mn;
                    if (wreg[j] > 0.f) { acc += wreg[j] * cb; Breg[j] = cb; }
                    Pprev[j] = cc;
                }
            }
        }
#pragma unroll
        for (int off = 16; off; off >>= 1)
            acc += __shfl_xor_sync(0xffffffffu, acc, off);

        if (lane == 0) {
            stcg_f32(&g_C[m * NN + n], acc);
            unsigned long long pk =
                ((unsigned long long)(unsigned)m << 32) |
                (unsigned long long)__float_as_uint(acc);
            sts_vol64(ring_base + (unsigned)(m * 32 + wid) * 8u, pk);
        }
        dmn = dnext;
    }
}

// ---------------- stage 5: terminal expectation ----------------------------
__global__ void __launch_bounds__(256) final_kernel(float* __restrict__ out) {
    int t = threadIdx.x;
    float v = g_fw[t] * g_C[(MM - 1) * NN + t];
#pragma unroll
    for (int off = 16; off; off >>= 1) v += __shfl_xor_sync(0xffffffffu, v, off);
    __shared__ float s[8];
    if ((t & 31) == 0) s[t >> 5] = v;
    __syncthreads();
    if (t < 8) {
        float z = s[t];
#pragma unroll
        for (int off = 4; off; off >>= 1) z += __shfl_xor_sync(0xffu, z, off);
        if (t == 0) out[0] = z;
    }
}

// ---------------- launch ----------------------------------------------------
extern "C" void kernel_launch(void* const* d_in, const int* in_sizes, int n_in,
                              void* d_out, int out_size) {
    const float* x = nullptr;
    const float* y = nullptr;
    const float* q = nullptr;
    for (int i = 0; i < n_in; i++) {
        if (in_sizes[i] == MM * DD)            x = (const float*)d_in[i];
        else if (in_sizes[i] == NN * DD)       y = (const float*)d_in[i];
        else if (in_sizes[i] == (NN + 1) * NN) q = (const float*)d_in[i];
    }
    float* out = (float*)d_out;

    const int ring_bytes = MM * 32 * (int)sizeof(unsigned long long);  // 128 KB
    cudaFuncSetAttribute(dp_kernel, cudaFuncAttributeMaxDynamicSharedMemorySize,
                         ring_bytes);

    init_kernel<<<(MM * NN + 255) / 256, 256>>>();

    dim3 dg(MM / 32, NN / 64);
    dist_kernel<<<dg, 256>>>(x, y);

    transpose_q<<<(NN * (NN + 1) + 255) / 256, 256>>>(q);
    scan_kernel<<<1, 320>>>();
    weights_kernel<<<NN * NN / 256, 256>>>(q);

    dp_kernel<<<8, 1024, ring_bytes>>>();

    final_kernel<<<1, 256>>>(out);
}

// round 7
// speedup vs baseline: 1.5217x; 1.5217x over previous
#include <cuda_runtime.h>
#include <math.h>

// Problem constants (fixed by the dataset)
#define MM 512
#define NN 256
#define DD 64
#define EPSV 1e-6f
#define INFV 1e30f
#define SENTU 0xFFC00001u   // NaN payload; never produced by the DP arithmetic
#define FULLM 0xffffffffu

// ---------------- device scratch (no allocations allowed) ----------------
__device__ float g_dists[MM * NN];          // d[m][n]
__device__ float g_qT[NN * (NN + 1)];       // qT[nb][i] = q[i][nb]
__device__ float g_p[NN + 1];               // reachability
__device__ float g_w[NN * NN];              // w[n][nb] (0 where not an edge)
__device__ float g_fw[NN];                  // final weights p_back[N][:]
__device__ float g_C[MM * NN];              // DP table (sentinel-initialized)

// ---------------- tiny asm helpers ----------------
__device__ __forceinline__ unsigned ldcg_u32(const float* p) {
    unsigned v;
    asm volatile("ld.global.cg.b32 %0, [%1];" : "=r"(v) : "l"(p));
    return v;
}
__device__ __forceinline__ void stcg_f32(float* p, float v) {
    asm volatile("st.global.cg.b32 [%0], %1;" :: "l"(p), "f"(v));
}
// sum -> lane 0 (other lanes get partial sums; only lane 0 uses the result)
__device__ __forceinline__ float warp_sum_to0(float v) {
    v += __shfl_down_sync(FULLM, v, 16);
    v += __shfl_down_sync(FULLM, v, 8);
    v += __shfl_down_sync(FULLM, v, 4);
    v += __shfl_down_sync(FULLM, v, 2);
    v += __shfl_down_sync(FULLM, v, 1);
    return v;
}

// ---------------- stage 0: fused sentinel-fill + q transpose ----------------
__global__ void __launch_bounds__(256) prep_kernel(const float* __restrict__ q) {
    int t = blockIdx.x * 256 + threadIdx.x;
    if (t < MM * NN) g_C[t] = __uint_as_float(SENTU);
    if (t < NN * (NN + 1)) {
        int nb = t / (NN + 1);
        int i  = t % (NN + 1);
        g_qT[t] = q[i * NN + nb];
    }
}

// ---------------- stage 1: pairwise L2 distances ----------
__global__ void __launch_bounds__(256) dist_kernel(const float* __restrict__ x,
                                                   const float* __restrict__ y) {
    __shared__ float xs[32][DD + 1];
    __shared__ float ys[64][DD + 1];
    int m0 = blockIdx.x * 32;
    int n0 = blockIdx.y * 64;
    int t = threadIdx.x;

    for (int i = t; i < 32 * DD; i += 256) xs[i / DD][i % DD] = x[(m0 + i / DD) * DD + i % DD];
    for (int i = t; i < 64 * DD; i += 256) ys[i / DD][i % DD] = y[(n0 + i / DD) * DD + i % DD];
    __syncthreads();

    int tn = t & 63;
    int tm = t >> 6;
    float acc[8];
#pragma unroll
    for (int r = 0; r < 8; r++) acc[r] = 0.f;

    for (int k = 0; k < DD; k++) {
        float yv = ys[tn][k];
#pragma unroll
        for (int r = 0; r < 8; r++) {
            float d = xs[tm * 8 + r][k] - yv;
            acc[r] = fmaf(d, d, acc[r]);
        }
    }
#pragma unroll
    for (int r = 0; r < 8; r++)
        g_dists[(m0 + tm * 8 + r) * NN + (n0 + tn)] = sqrtf(acc[r]);
}

// ---------------- stage 2: blocked forward-substitution reachability scan ---
// Block of 32 sequential steps: phase 1 (warp 0) runs the 32-step chain on the
// 32 in-block elements via shfl (exact reference order); phase 2 (all threads)
// applies the rank-32 update to the remaining 225 elements, accumulating the
// 32 steps in ascending order (identical rounding order to the reference).
__global__ void __launch_bounds__(256) scan_kernel() {
    __shared__ float sp[NN + 1];
    __shared__ float ps[32];
    int t = threadIdx.x;
    sp[t] = (t == 0) ? 1.f : 0.f;
    if (t == 0) sp[NN] = 0.f;
    __syncthreads();

    for (int blk = 0; blk < 8; blk++) {
        int base = blk * 32;
        if (t < 32) {
            float pl = sp[base + t];
#pragma unroll
            for (int s = 0; s < 32; s++) {
                float pnb = __shfl_sync(FULLM, pl, s);   // pre-update p[base+s]
                float qv = __ldg(&g_qT[(base + s) * (NN + 1) + base + t]);
                pl = fmaf(pnb, qv, pl);
                if (t == 0) ps[s] = pnb;
            }
            sp[base + t] = pl;
        }
        __syncthreads();
        if (t < 225) {
            int i = (t < base) ? t : t + 32;   // all elements outside the block
            float pi = sp[i];
#pragma unroll
            for (int s = 0; s < 32; s++)
                pi = fmaf(ps[s], __ldg(&g_qT[(base + s) * (NN + 1) + i]), pi);
            sp[i] = pi;
        }
        __syncthreads();
    }

    g_p[t] = sp[t];
    if (t == 0) g_p[NN] = sp[NN];
}

// ---------------- stage 3: mixing weights + terminal weights ---------------
__global__ void weights_kernel(const float* __restrict__ q) {
    int idx = blockIdx.x * 256 + threadIdx.x;  // N*N threads
    int n  = idx >> 8;
    int nb = idx & 255;
    float pb = g_p[nb] * q[n * NN + nb] / (g_p[n] + EPSV);
    g_w[idx] = (nb < n && pb > 0.f) ? pb : 0.f;
    if (n == 0) {
        g_fw[nb] = g_p[nb] * q[NN * NN + nb] / (g_p[NN] + EPSV);
    }
}

// ---------------- stage 4: pipelined fence-free wavefront DP ----------------
// One warp = one CTA = one column (R4 topology: each column owns a full SM's
// issue bandwidth). Handoffs via sentinel-valued g_C in L2 (st.cg / ld.cg).
// Software pipeline: row m+1 chunk loads are issued BEFORE row m is verified
// and computed, so in steady state (predecessor several rows ahead) the fast
// path never waits on memory: 8 compares + 1 ballot. Slow path (pipeline fill
// at startup) reloads with __nanosleep backoff and ONLY waits on cells of
// strictly earlier columns (deadlock-freedom by induction over columns).
__global__ void __launch_bounds__(32, 16) dp_kernel() {
    const int lane = threadIdx.x;
    const int n = blockIdx.x;

    if (n == 0) {
        // column 0: C[m][0] = running sum of d[m][0] via warp inclusive scan
        float run = 0.f;
        for (int mb = 0; mb < MM; mb += 32) {
            float dv = g_dists[(mb + lane) * NN];
#pragma unroll
            for (int off = 1; off < 32; off <<= 1) {
                float t = __shfl_up_sync(FULLM, dv, off);
                if (lane >= off) dv += t;
            }
            float val = run + dv;
            stcg_f32(&g_C[(mb + lane) * NN], val);
            run = __shfl_sync(FULLM, val, 31);
        }
        return;
    }

    float wreg[8], Breg[8], Pprev[8];
#pragma unroll
    for (int j = 0; j < 8; j++) {
        int idx = j * 32 + lane;
        wreg[j]  = (idx < n) ? g_w[n * NN + idx] : 0.f;
        Breg[j]  = INFV;
        Pprev[j] = INFV;
    }

    const int jmax = (n - 1) >> 5;

    // prologue: issue loads for row 0
    unsigned cur[8], nxt[8];
#pragma unroll
    for (int j = 0; j < 8; j++)
        if (j <= jmax) cur[j] = ldcg_u32(&g_C[j * 32 + lane]);
    float dmn = __ldg(&g_dists[n]);
    float dnx = 0.f;

    for (int m = 0; m < MM; m++) {
        // prefetch row m+1 (hides L2 latency under verify+compute of row m)
        if (m + 1 < MM) {
#pragma unroll
            for (int j = 0; j < 8; j++)
                if (j <= jmax) nxt[j] = ldcg_u32(&g_C[(m + 1) * NN + j * 32 + lane]);
            dnx = __ldg(&g_dists[(m + 1) * NN + n]);
        }

        // verify row m: fast path is one combined ballot
        {
            bool bad = false;
#pragma unroll
            for (int j = 0; j < 8; j++)
                if (j <= jmax) bad |= ((j * 32 + lane) < n) && (cur[j] == SENTU);
            if (__any_sync(FULLM, bad)) {
                const float* Crow = &g_C[m * NN];
                for (;;) {
                    int again = 0;
#pragma unroll
                    for (int j = 0; j < 8; j++) {
                        if (j <= jmax) {
                            bool need = ((j * 32 + lane) < n) && (cur[j] == SENTU);
                            if (__any_sync(FULLM, need)) {
                                if (need) cur[j] = ldcg_u32(&Crow[j * 32 + lane]);
                                again = 1;
                            }
                        }
                    }
                    if (!again) break;
                    __nanosleep(30);
                }
            }
        }

        // compute cell (m, n)
        float acc = 0.f;
#pragma unroll
        for (int j = 0; j < 8; j++) {
            int idx = j * 32 + lane;
            if (idx < n) {
                float cc = __uint_as_float(cur[j]);
                float mn = fminf(cc, fminf(Pprev[j], Breg[j]));
                float cb = dmn + mn;
                if (wreg[j] > 0.f) { acc += wreg[j] * cb; Breg[j] = cb; }
                Pprev[j] = cc;
            }
        }
        acc = warp_sum_to0(acc);

        if (lane == 0) stcg_f32(&g_C[m * NN + n], acc);

        // rotate pipeline registers
#pragma unroll
        for (int j = 0; j < 8; j++) cur[j] = nxt[j];
        dmn = dnx;
    }
}

// ---------------- stage 5: terminal expectation ----------------------------
__global__ void __launch_bounds__(256) final_kernel(float* __restrict__ out) {
    int t = threadIdx.x;
    float v = g_fw[t] * g_C[(MM - 1) * NN + t];
#pragma unroll
    for (int off = 16; off; off >>= 1) v += __shfl_xor_sync(FULLM, v, off);
    __shared__ float s[8];
    if ((t & 31) == 0) s[t >> 5] = v;
    __syncthreads();
    if (t < 8) {
        float z = s[t];
#pragma unroll
        for (int off = 4; off; off >>= 1) z += __shfl_xor_sync(0xffu, z, off);
        if (t == 0) out[0] = z;
    }
}

// ---------------- launch ----------------------------------------------------
extern "C" void kernel_launch(void* const* d_in, const int* in_sizes, int n_in,
                              void* d_out, int out_size) {
    const float* x = nullptr;
    const float* y = nullptr;
    const float* q = nullptr;
    for (int i = 0; i < n_in; i++) {
        if (in_sizes[i] == MM * DD)            x = (const float*)d_in[i];
        else if (in_sizes[i] == NN * DD)       y = (const float*)d_in[i];
        else if (in_sizes[i] == (NN + 1) * NN) q = (const float*)d_in[i];
    }
    float* out = (float*)d_out;

    prep_kernel<<<(MM * NN + 255) / 256, 256>>>(q);

    dim3 dg(MM / 32, NN / 64);
    dist_kernel<<<dg, 256>>>(x, y);

    scan_kernel<<<1, 256>>>();
    weights_kernel<<<NN * NN / 256, 256>>>(q);

    dp_kernel<<<NN, 32>>>();    // one warp per column, one column per SM slot

    final_kernel<<<1, 256>>>(out);
}